// round 1
// baseline (speedup 1.0000x reference)
#include <cuda_runtime.h>
#include <math.h>

#define NN   4096
#define DD   128
#define HH   128
#define EQN  16384
#define MAXE 131072
#define MAXNNZ 262144

// ---------------- device scratch (no allocations allowed) ----------------
static __device__ float  g_vals[MAXE];      // MLP output per aug edge
static __device__ float  g_aval[MAXE];      // unnormalized A_enh value per aug edge
static __device__ float  g_d[NN];           // row sums of A_enh
static __device__ float  g_invd[NN];
static __device__ float  g_pi[NN];
static __device__ int    g_deg[NN];
static __device__ int    g_rowstart[NN + 1];
static __device__ int    g_rowpos[NN];
static __device__ int    g_cols[MAXNNZ];
static __device__ float  g_cvals[MAXNNZ];
static __device__ int    g_qcnt[NN];
static __device__ int    g_qstart[NN + 1];
static __device__ int    g_qpos[NN];
static __device__ int    g_qid[EQN];
static __device__ float  g_pval[EQN];       // P[q0][q1] per query
static __device__ double g_G1, g_G2, g_sumpi;
static __device__ float  g_sumd;
static __device__ float  g_XW[NN * HH];     // X @ W1[:128,:]  (node-factored half of layer 1)
static __device__ int    g_is64;

// index accessor: buffers may be int32 (jax x64 off) or int64. If int64 (LE),
// low word at 2*k. g_is64 set by k_detect.
__device__ __forceinline__ int idx_at(const int* __restrict__ p, int k) {
    return g_is64 ? p[2 * k] : p[k];
}

// ---------------- kernels ----------------

// aug_edges is strictly upper-triangular => e1 >= 1 always. If the buffer is
// int32, odd words are e1 values (all nonzero). If int64, odd words are high
// halves (all zero). Check 1024 of them.
__global__ void k_detect(const int* __restrict__ AE) {
    __shared__ int any;
    int t = threadIdx.x;
    if (t == 0) any = 0;
    __syncthreads();
    int loc = 0;
    for (int q = t; q < 1024; q += blockDim.x)
        if (AE[2 * q + 1] != 0) loc = 1;
    if (loc) atomicOr(&any, 1);
    __syncthreads();
    if (t == 0) g_is64 = (any == 0) ? 1 : 0;
}

__global__ void k_init() {
    int i = blockIdx.x * blockDim.x + threadIdx.x;
    if (i < NN) { g_d[i] = 1.0f; g_deg[i] = 1; g_qcnt[i] = 0; }
    if (i == 0) { g_G1 = 0.0; g_G2 = 0.0; g_sumpi = 0.0; }
}

// XW = X @ W1[0:128, :]   (4096x128 @ 128x128)
__global__ void __launch_bounds__(128) k_xw(const float* __restrict__ X,
                                            const float* __restrict__ W1) {
    __shared__ float xs[32 * 132];
    int t = threadIdx.x;
    int r0 = blockIdx.x * 32;
    int le = t >> 2, c = t & 3;
    const float* xr = X + (size_t)(r0 + le) * DD;
#pragma unroll
    for (int i = 0; i < 32; i++) { int k = c * 32 + i; xs[le * 132 + k] = xr[k]; }
    __syncthreads();
    float acc[32];
#pragma unroll
    for (int e = 0; e < 32; e++) acc[e] = 0.0f;
    for (int k = 0; k < 128; k++) {
        float w = W1[k * 128 + t];
#pragma unroll
        for (int e = 0; e < 32; e++) acc[e] = fmaf(w, xs[e * 132 + k], acc[e]);
    }
#pragma unroll
    for (int e = 0; e < 32; e++) g_XW[(size_t)(r0 + e) * 128 + t] = acc[e];
}

// Edge MLP: vals = sigmoid(z1-z0) of softmax head. 32 edges per block.
__global__ void __launch_bounds__(128) k_mlp(const float* __restrict__ X,
                                             const int* __restrict__ AE,
                                             const float* __restrict__ W1,
                                             const float* __restrict__ b1,
                                             const float* __restrict__ W2,
                                             const float* __restrict__ b2,
                                             const float* __restrict__ W3,
                                             const float* __restrict__ b3,
                                             int E) {
    __shared__ float bufA[32 * 132];   // |x0-x1| features (stride 132), later h2 (stride 129)
    __shared__ float h1[32 * 128];
    __shared__ int   su[32], sv[32];
    int t = threadIdx.x;
    int e0 = blockIdx.x * 32;
    int le = t >> 2, c = t & 3;
    int e = e0 + le;
    int u = 0, v = 0;
    if (e < E) { u = idx_at(AE, 2 * e); v = idx_at(AE, 2 * e + 1); }
    if (c == 0) { su[le] = u; sv[le] = v; }
    const float* x0 = X + (size_t)u * DD;
    const float* x1 = X + (size_t)v * DD;
#pragma unroll
    for (int i = 0; i < 32; i++) {
        int k = c * 32 + i;
        float a = x0[k], b = x1[k];
        bufA[le * 132 + k] = (e < E) ? fabsf(a - b) : 0.0f;
    }
    __syncthreads();

    // layer 1: acc = b1 + XW[u] + XW[v] + |x0-x1| @ W1[128:256,:]
    float acc[32];
    {
        float bb = b1[t];
#pragma unroll
        for (int ee = 0; ee < 32; ee++)
            acc[ee] = bb + g_XW[(size_t)su[ee] * 128 + t] + g_XW[(size_t)sv[ee] * 128 + t];
    }
    for (int k = 0; k < 128; k++) {
        float w = W1[(128 + k) * 128 + t];
#pragma unroll
        for (int ee = 0; ee < 32; ee++) acc[ee] = fmaf(w, bufA[ee * 132 + k], acc[ee]);
    }
#pragma unroll
    for (int ee = 0; ee < 32; ee++) h1[ee * 128 + t] = fmaxf(acc[ee], 0.0f);
    __syncthreads();   // h1 ready; bufA reads done -> safe to overwrite bufA later

    // layer 2
    {
        float bb = b2[t];
#pragma unroll
        for (int ee = 0; ee < 32; ee++) acc[ee] = bb;
    }
    for (int k = 0; k < 128; k++) {
        float w = W2[k * 128 + t];
#pragma unroll
        for (int ee = 0; ee < 32; ee++) acc[ee] = fmaf(w, h1[ee * 128 + k], acc[ee]);
    }
#pragma unroll
    for (int ee = 0; ee < 32; ee++) bufA[ee * 129 + t] = fmaxf(acc[ee], 0.0f); // h2
    __syncthreads();

    // head: vals = sigmoid(h2 . (W3[:,1]-W3[:,0]) + (b3[1]-b3[0]))
    if (t < 32) {
        float z = b3[1] - b3[0];
        for (int k = 0; k < 128; k++) {
            float wd = W3[2 * k + 1] - W3[2 * k + 0];
            z = fmaf(bufA[t * 129 + k], wd, z);
        }
        int eo = e0 + t;
        if (eo < E) g_vals[eo] = 1.0f / (1.0f + __expf(-z));
    }
}

// per-edge A_enh value + degree/rowsum accumulation
__global__ void k_edge(const float* __restrict__ A, const float* __restrict__ S,
                       const int* __restrict__ AE, int E) {
    int e = blockIdx.x * blockDim.x + threadIdx.x;
    if (e >= E) return;
    int u = idx_at(AE, 2 * e), v = idx_at(AE, 2 * e + 1);
    size_t idx = ((size_t)u << 12) + (size_t)v;
    float a = 0.5f * A[idx] + 0.25f * g_vals[e] + 0.25f * S[idx];
    g_aval[e] = a;
    atomicAdd(&g_d[u], a);
    atomicAdd(&g_d[v], a);
    atomicAdd(&g_deg[u], 1);
    atomicAdd(&g_deg[v], 1);
}

__global__ void k_qcnt(const int* __restrict__ Q) {
    int q = blockIdx.x * blockDim.x + threadIdx.x;
    if (q >= EQN) return;
    atomicAdd(&g_qcnt[idx_at(Q, 2 * q)], 1);
}

// single-block exclusive scans (rows, query rows) + sum(d)
__global__ void __launch_bounds__(1024) k_scan() {
    __shared__ int sm[1024];
    __shared__ float sf[1024];
    int t = threadIdx.x;
    int v[4];

    // --- row degree scan ---
    int s = 0;
#pragma unroll
    for (int j = 0; j < 4; j++) { v[j] = g_deg[4 * t + j]; s += v[j]; }
    sm[t] = s;
    __syncthreads();
    for (int off = 1; off < 1024; off <<= 1) {
        int x = (t >= off) ? sm[t - off] : 0;
        __syncthreads();
        sm[t] += x;
        __syncthreads();
    }
    {
        int run = sm[t] - s;
#pragma unroll
        for (int j = 0; j < 4; j++) { g_rowstart[4 * t + j] = run; g_rowpos[4 * t + j] = run; run += v[j]; }
        if (t == 1023) g_rowstart[NN] = sm[1023];
    }
    __syncthreads();

    // --- query count scan ---
    s = 0;
#pragma unroll
    for (int j = 0; j < 4; j++) { v[j] = g_qcnt[4 * t + j]; s += v[j]; }
    sm[t] = s;
    __syncthreads();
    for (int off = 1; off < 1024; off <<= 1) {
        int x = (t >= off) ? sm[t - off] : 0;
        __syncthreads();
        sm[t] += x;
        __syncthreads();
    }
    {
        int run = sm[t] - s;
#pragma unroll
        for (int j = 0; j < 4; j++) { g_qstart[4 * t + j] = run; g_qpos[4 * t + j] = run; run += v[j]; }
        if (t == 1023) g_qstart[NN] = sm[1023];
    }
    __syncthreads();

    // --- sum(d) ---
    float fs = 0.0f;
#pragma unroll
    for (int j = 0; j < 4; j++) fs += g_d[4 * t + j];
    sf[t] = fs;
    __syncthreads();
    for (int off = 512; off; off >>= 1) {
        if (t < off) sf[t] += sf[t + off];
        __syncthreads();
    }
    if (t == 0) g_sumd = sf[0];
}

// pi, inv_d, sum(pi), and diagonal CSR entries
__global__ void k_pi() {
    int i = blockIdx.x * blockDim.x + threadIdx.x;
    if (i >= NN) return;
    float di = g_d[i];
    float p = di / g_sumd;
    g_pi[i] = p;
    g_invd[i] = 1.0f / di;
    atomicAdd(&g_sumpi, (double)p);
    int idx = atomicAdd(&g_rowpos[i], 1);
    g_cols[idx] = i;
    g_cvals[idx] = 1.0f;
}

__global__ void k_scatter(const int* __restrict__ AE, int E) {
    int e = blockIdx.x * blockDim.x + threadIdx.x;
    if (e >= E) return;
    int u = idx_at(AE, 2 * e), v = idx_at(AE, 2 * e + 1);
    float a = g_aval[e];
    int i1 = atomicAdd(&g_rowpos[u], 1); g_cols[i1] = v; g_cvals[i1] = a;
    int i2 = atomicAdd(&g_rowpos[v], 1); g_cols[i2] = u; g_cvals[i2] = a;
}

__global__ void k_qscatter(const int* __restrict__ Q) {
    int q = blockIdx.x * blockDim.x + threadIdx.x;
    if (q >= EQN) return;
    int i = idx_at(Q, 2 * q);
    int idx = atomicAdd(&g_qpos[i], 1);
    g_qid[idx] = q;
}

// One block per row i: sparse row of P = M@M into dense smem accumulator,
// then dense scan for rowsum & sum_j (P_ij - pi_j)^2, plus query gathers.
__global__ void __launch_bounds__(256) k_row(const int* __restrict__ Q) {
    __shared__ float acc[NN];
    __shared__ float s1[8], s2[8];
    int i = blockIdx.x;
    int t = threadIdx.x;
    for (int c = t; c < NN; c += 256) acc[c] = 0.0f;
    __syncthreads();

    int rs = g_rowstart[i], re = g_rowstart[i + 1];
    float idi = g_invd[i];
    int warp = t >> 5, lane = t & 31;
    for (int jj = rs + warp; jj < re; jj += 8) {
        int j = g_cols[jj];
        float sscale = g_cvals[jj] * idi * g_invd[j];   // M[i,j] * (1/d_j)
        int js = g_rowstart[j], je = g_rowstart[j + 1];
        for (int kk = js + lane; kk < je; kk += 32)
            atomicAdd(&acc[g_cols[kk]], sscale * g_cvals[kk]);
    }
    __syncthreads();

    float srow = 0.0f, ssq = 0.0f;
    for (int c = t; c < NN; c += 256) {
        float a = acc[c];
        srow += a;
        float dd = a - g_pi[c];
        ssq = fmaf(dd, dd, ssq);
    }
#pragma unroll
    for (int o = 16; o; o >>= 1) {
        srow += __shfl_down_sync(0xffffffffu, srow, o);
        ssq  += __shfl_down_sync(0xffffffffu, ssq, o);
    }
    if (lane == 0) { s1[warp] = srow; s2[warp] = ssq; }
    __syncthreads();
    if (t == 0) {
        float S1 = 0.0f, S2 = 0.0f;
#pragma unroll
        for (int w = 0; w < 8; w++) { S1 += s1[w]; S2 += s2[w]; }
        float pii = g_pi[i];
        atomicAdd(&g_G1, (double)pii * (double)S1);
        atomicAdd(&g_G2, (double)pii * (double)pii * (double)S2);
    }
    // queries whose q0 == i
    int qs = g_qstart[i], qe = g_qstart[i + 1];
    for (int q = qs + t; q < qe; q += 256) {
        int qq = g_qid[q];
        int j1 = idx_at(Q, 2 * qq + 1);
        g_pval[qq] = acc[j1];
    }
}

__global__ void k_final(const int* __restrict__ Q, float* __restrict__ out) {
    int q = blockIdx.x * blockDim.x + threadIdx.x;
    if (q >= EQN) return;
    double n2 = (double)NN * (double)NN;
    double sp = g_sumpi;
    double mean = (g_G1 - sp * sp) / n2;
    double var = (g_G2 - n2 * mean * mean) / (n2 - 1.0);
    double istd = rsqrt(var);
    int i = idx_at(Q, 2 * q), j = idx_at(Q, 2 * q + 1);
    double r = (double)g_pi[i] * ((double)g_pval[q] - (double)g_pi[j]);
    out[q] = (float)((r - mean) * istd);
}

// ---------------- launch ----------------
extern "C" void kernel_launch(void* const* d_in, const int* in_sizes, int n_in,
                              void* d_out, int out_size) {
    const float* X  = (const float*)d_in[0];
    const float* A  = (const float*)d_in[1];
    const float* S  = (const float*)d_in[2];
    // d_in[3] = aug_mask (unused: S is pre-masked, A subset of mask)
    const int*   AE = (const int*)d_in[4];
    const int*   Q  = (const int*)d_in[5];
    const float* W1 = (const float*)d_in[6];
    const float* b1 = (const float*)d_in[7];
    const float* W2 = (const float*)d_in[8];
    const float* b2 = (const float*)d_in[9];
    const float* W3 = (const float*)d_in[10];
    const float* b3 = (const float*)d_in[11];
    float* out = (float*)d_out;
    int E = in_sizes[4] / 2;

    k_detect<<<1, 256>>>(AE);
    k_init<<<(NN + 255) / 256, 256>>>();
    k_xw<<<NN / 32, 128>>>(X, W1);
    k_mlp<<<(E + 31) / 32, 128>>>(X, AE, W1, b1, W2, b2, W3, b3, E);
    k_edge<<<(E + 255) / 256, 256>>>(A, S, AE, E);
    k_qcnt<<<(EQN + 255) / 256, 256>>>(Q);
    k_scan<<<1, 1024>>>();
    k_pi<<<(NN + 255) / 256, 256>>>();
    k_scatter<<<(E + 255) / 256, 256>>>(AE, E);
    k_qscatter<<<(EQN + 255) / 256, 256>>>(Q);
    k_row<<<NN, 256>>>(Q);
    k_final<<<(EQN + 255) / 256, 256>>>(Q, out);
}

// round 2
// speedup vs baseline: 1.7783x; 1.7783x over previous
#include <cuda_runtime.h>
#include <math.h>

#define NN   4096
#define DD   128
#define HH   128
#define EQN  16384
#define MAXE 131072
#define MAXNNZ 262144

// ---------------- device scratch (no allocations allowed) ----------------
static __device__ float  g_vals[MAXE];
static __device__ float  g_aval[MAXE];
static __device__ float  g_d[NN];
static __device__ float  g_invd[NN];
static __device__ float  g_pi[NN];
static __device__ int    g_deg[NN];
static __device__ int    g_rowstart[NN + 1];
static __device__ int    g_rowpos[NN];
static __device__ int    g_cols[MAXNNZ];
static __device__ float  g_cvals[MAXNNZ];
static __device__ int    g_qcnt[NN];
static __device__ int    g_qstart[NN + 1];
static __device__ int    g_qpos[NN];
static __device__ int    g_qid[EQN];
static __device__ float  g_pval[EQN];
static __device__ double g_G1, g_G2, g_sumpi;
static __device__ float  g_sumd;
static __device__ float  g_XW[NN * HH];     // X @ W1[:128,:]
static __device__ int    g_is64;

__device__ __forceinline__ int idx_at(const int* __restrict__ p, int k) {
    return g_is64 ? p[2 * k] : p[k];
}

// ---- packed fp32 helpers (Blackwell f32x2) ----
__device__ __forceinline__ unsigned long long pk2(float lo, float hi) {
    unsigned long long r;
    asm("mov.b64 %0, {%1, %2};" : "=l"(r) : "f"(lo), "f"(hi));
    return r;
}
__device__ __forceinline__ void upk2(unsigned long long v, float& lo, float& hi) {
    asm("mov.b64 {%0, %1}, %2;" : "=f"(lo), "=f"(hi) : "l"(v));
}
__device__ __forceinline__ void ffma2(unsigned long long& acc,
                                      unsigned long long a, unsigned long long b) {
    asm("fma.rn.f32x2 %0, %1, %2, %0;" : "+l"(acc) : "l"(a), "l"(b));
}

// ---------------- kernels ----------------

__global__ void k_detect(const int* __restrict__ AE) {
    __shared__ int any;
    int t = threadIdx.x;
    if (t == 0) any = 0;
    __syncthreads();
    int loc = 0;
    for (int q = t; q < 1024; q += blockDim.x)
        if (AE[2 * q + 1] != 0) loc = 1;
    if (loc) atomicOr(&any, 1);
    __syncthreads();
    if (t == 0) g_is64 = (any == 0) ? 1 : 0;
}

__global__ void k_init() {
    int i = blockIdx.x * blockDim.x + threadIdx.x;
    if (i < NN) { g_d[i] = 1.0f; g_deg[i] = 1; g_qcnt[i] = 0; }
    if (i == 0) { g_G1 = 0.0; g_G2 = 0.0; g_sumpi = 0.0; }
}

// XW = X @ W1[0:128, :]
__global__ void __launch_bounds__(128) k_xw(const float* __restrict__ X,
                                            const float* __restrict__ W1) {
    __shared__ float xs[32 * 132];
    int t = threadIdx.x;
    int r0 = blockIdx.x * 32;
    int le = t >> 2, c = t & 3;
    const float* xr = X + (size_t)(r0 + le) * DD;
#pragma unroll
    for (int i = 0; i < 32; i++) { int k = c * 32 + i; xs[le * 132 + k] = xr[k]; }
    __syncthreads();
    float acc[32];
#pragma unroll
    for (int e = 0; e < 32; e++) acc[e] = 0.0f;
    for (int k = 0; k < 128; k++) {
        float w = W1[k * 128 + t];
#pragma unroll
        for (int e = 0; e < 32; e++) acc[e] = fmaf(w, xs[e * 132 + k], acc[e]);
    }
#pragma unroll
    for (int e = 0; e < 32; e++) g_XW[(size_t)(r0 + e) * 128 + t] = acc[e];
}

// Edge MLP, f32x2 version. 32 edges/block, 64 threads, thread t owns cols 2t,2t+1.
// Features/activations stored transposed in smem: buf[k*36 + edge].
#define FS 36
__global__ void __launch_bounds__(64) k_mlp(const float* __restrict__ X,
                                            const int* __restrict__ AE,
                                            const float* __restrict__ W1,
                                            const float* __restrict__ b1,
                                            const float* __restrict__ W2,
                                            const float* __restrict__ b2,
                                            const float* __restrict__ W3,
                                            const float* __restrict__ b3,
                                            int E) {
    __shared__ float feat_s[128 * FS];   // |x0-x1| features, later h2
    __shared__ float h1_s[128 * FS];
    __shared__ int   su[32], sv[32];
    int t = threadIdx.x;                 // 0..63
    int e0 = blockIdx.x * 32;

    // ---- feature build: thread (le = t>>1, c = t&1) covers edge le, k-half c
    {
        int le = t >> 1, c = t & 1;
        int e = e0 + le;
        int u = 0, v = 0;
        if (e < E) { u = idx_at(AE, 2 * e); v = idx_at(AE, 2 * e + 1); }
        if (c == 0) { su[le] = u; sv[le] = v; }
        const float4* x04 = (const float4*)(X + (size_t)u * DD + c * 64);
        const float4* x14 = (const float4*)(X + (size_t)v * DD + c * 64);
        bool ok = (e < E);
#pragma unroll
        for (int i = 0; i < 16; i++) {
            float4 a = x04[i], b = x14[i];
            int k = c * 64 + 4 * i;
            feat_s[(k + 0) * FS + le] = ok ? fabsf(a.x - b.x) : 0.0f;
            feat_s[(k + 1) * FS + le] = ok ? fabsf(a.y - b.y) : 0.0f;
            feat_s[(k + 2) * FS + le] = ok ? fabsf(a.z - b.z) : 0.0f;
            feat_s[(k + 3) * FS + le] = ok ? fabsf(a.w - b.w) : 0.0f;
        }
    }
    __syncthreads();

    unsigned long long accA[16], accB[16];  // accA: col 2t, accB: col 2t+1; pairs of edges

    // ---- layer 1: acc = b1 + XW[u] + XW[v] + feat @ W1[128:256,:]
    {
        float2 bb = *(const float2*)&b1[2 * t];
#pragma unroll
        for (int p = 0; p < 16; p++) {
            int ea = 2 * p, eb = 2 * p + 1;
            float2 ua = *(const float2*)&g_XW[(size_t)su[ea] * 128 + 2 * t];
            float2 va = *(const float2*)&g_XW[(size_t)sv[ea] * 128 + 2 * t];
            float2 ub = *(const float2*)&g_XW[(size_t)su[eb] * 128 + 2 * t];
            float2 vb = *(const float2*)&g_XW[(size_t)sv[eb] * 128 + 2 * t];
            accA[p] = pk2(bb.x + ua.x + va.x, bb.x + ub.x + vb.x);
            accB[p] = pk2(bb.y + ua.y + va.y, bb.y + ub.y + vb.y);
        }
    }
#pragma unroll 2
    for (int k = 0; k < 128; k++) {
        float2 w = *(const float2*)&W1[(size_t)(128 + k) * 128 + 2 * t];
        unsigned long long w0 = pk2(w.x, w.x);
        unsigned long long w1 = pk2(w.y, w.y);
        const double2* f4 = (const double2*)&feat_s[k * FS];
#pragma unroll
        for (int q = 0; q < 8; q++) {
            double2 d = f4[q];
            unsigned long long flo = __double_as_longlong(d.x);
            unsigned long long fhi = __double_as_longlong(d.y);
            ffma2(accA[2 * q], flo, w0);
            ffma2(accA[2 * q + 1], fhi, w0);
            ffma2(accB[2 * q], flo, w1);
            ffma2(accB[2 * q + 1], fhi, w1);
        }
    }
    // relu -> h1 (transposed)
#pragma unroll
    for (int p = 0; p < 16; p++) {
        float a0, a1, c0, c1;
        upk2(accA[p], a0, a1);
        upk2(accB[p], c0, c1);
        float2 ra = make_float2(fmaxf(a0, 0.0f), fmaxf(a1, 0.0f));
        float2 rb = make_float2(fmaxf(c0, 0.0f), fmaxf(c1, 0.0f));
        *(float2*)&h1_s[(2 * t) * FS + 2 * p]     = ra;
        *(float2*)&h1_s[(2 * t + 1) * FS + 2 * p] = rb;
    }
    __syncthreads();

    // ---- layer 2
    {
        float2 bb = *(const float2*)&b2[2 * t];
#pragma unroll
        for (int p = 0; p < 16; p++) {
            accA[p] = pk2(bb.x, bb.x);
            accB[p] = pk2(bb.y, bb.y);
        }
    }
#pragma unroll 2
    for (int k = 0; k < 128; k++) {
        float2 w = *(const float2*)&W2[(size_t)k * 128 + 2 * t];
        unsigned long long w0 = pk2(w.x, w.x);
        unsigned long long w1 = pk2(w.y, w.y);
        const double2* f4 = (const double2*)&h1_s[k * FS];
#pragma unroll
        for (int q = 0; q < 8; q++) {
            double2 d = f4[q];
            unsigned long long flo = __double_as_longlong(d.x);
            unsigned long long fhi = __double_as_longlong(d.y);
            ffma2(accA[2 * q], flo, w0);
            ffma2(accA[2 * q + 1], fhi, w0);
            ffma2(accB[2 * q], flo, w1);
            ffma2(accB[2 * q + 1], fhi, w1);
        }
    }
    // relu -> h2 into feat_s (transposed)
#pragma unroll
    for (int p = 0; p < 16; p++) {
        float a0, a1, c0, c1;
        upk2(accA[p], a0, a1);
        upk2(accB[p], c0, c1);
        float2 ra = make_float2(fmaxf(a0, 0.0f), fmaxf(a1, 0.0f));
        float2 rb = make_float2(fmaxf(c0, 0.0f), fmaxf(c1, 0.0f));
        *(float2*)&feat_s[(2 * t) * FS + 2 * p]     = ra;
        *(float2*)&feat_s[(2 * t + 1) * FS + 2 * p] = rb;
    }
    __syncthreads();

    // ---- head: vals = sigmoid(h2 . (W3[:,1]-W3[:,0]) + (b3[1]-b3[0]))
    if (t < 32) {
        float z = b3[1] - b3[0];
        for (int k = 0; k < 128; k++) {
            float wd = W3[2 * k + 1] - W3[2 * k + 0];
            z = fmaf(feat_s[k * FS + t], wd, z);
        }
        int eo = e0 + t;
        if (eo < E) g_vals[eo] = 1.0f / (1.0f + __expf(-z));
    }
}

__global__ void k_edge(const float* __restrict__ A, const float* __restrict__ S,
                       const int* __restrict__ AE, int E) {
    int e = blockIdx.x * blockDim.x + threadIdx.x;
    if (e >= E) return;
    int u = idx_at(AE, 2 * e), v = idx_at(AE, 2 * e + 1);
    size_t idx = ((size_t)u << 12) + (size_t)v;
    float a = 0.5f * A[idx] + 0.25f * g_vals[e] + 0.25f * S[idx];
    g_aval[e] = a;
    atomicAdd(&g_d[u], a);
    atomicAdd(&g_d[v], a);
    atomicAdd(&g_deg[u], 1);
    atomicAdd(&g_deg[v], 1);
}

__global__ void k_qcnt(const int* __restrict__ Q) {
    int q = blockIdx.x * blockDim.x + threadIdx.x;
    if (q >= EQN) return;
    atomicAdd(&g_qcnt[idx_at(Q, 2 * q)], 1);
}

__global__ void __launch_bounds__(1024) k_scan() {
    __shared__ int sm[1024];
    __shared__ float sf[1024];
    int t = threadIdx.x;
    int v[4];

    int s = 0;
#pragma unroll
    for (int j = 0; j < 4; j++) { v[j] = g_deg[4 * t + j]; s += v[j]; }
    sm[t] = s;
    __syncthreads();
    for (int off = 1; off < 1024; off <<= 1) {
        int x = (t >= off) ? sm[t - off] : 0;
        __syncthreads();
        sm[t] += x;
        __syncthreads();
    }
    {
        int run = sm[t] - s;
#pragma unroll
        for (int j = 0; j < 4; j++) { g_rowstart[4 * t + j] = run; g_rowpos[4 * t + j] = run; run += v[j]; }
        if (t == 1023) g_rowstart[NN] = sm[1023];
    }
    __syncthreads();

    s = 0;
#pragma unroll
    for (int j = 0; j < 4; j++) { v[j] = g_qcnt[4 * t + j]; s += v[j]; }
    sm[t] = s;
    __syncthreads();
    for (int off = 1; off < 1024; off <<= 1) {
        int x = (t >= off) ? sm[t - off] : 0;
        __syncthreads();
        sm[t] += x;
        __syncthreads();
    }
    {
        int run = sm[t] - s;
#pragma unroll
        for (int j = 0; j < 4; j++) { g_qstart[4 * t + j] = run; g_qpos[4 * t + j] = run; run += v[j]; }
        if (t == 1023) g_qstart[NN] = sm[1023];
    }
    __syncthreads();

    float fs = 0.0f;
#pragma unroll
    for (int j = 0; j < 4; j++) fs += g_d[4 * t + j];
    sf[t] = fs;
    __syncthreads();
    for (int off = 512; off; off >>= 1) {
        if (t < off) sf[t] += sf[t + off];
        __syncthreads();
    }
    if (t == 0) g_sumd = sf[0];
}

__global__ void k_pi() {
    int i = blockIdx.x * blockDim.x + threadIdx.x;
    if (i >= NN) return;
    float di = g_d[i];
    float p = di / g_sumd;
    g_pi[i] = p;
    g_invd[i] = 1.0f / di;
    atomicAdd(&g_sumpi, (double)p);
    int idx = atomicAdd(&g_rowpos[i], 1);
    g_cols[idx] = i;
    g_cvals[idx] = 1.0f;
}

__global__ void k_scatter(const int* __restrict__ AE, int E) {
    int e = blockIdx.x * blockDim.x + threadIdx.x;
    if (e >= E) return;
    int u = idx_at(AE, 2 * e), v = idx_at(AE, 2 * e + 1);
    float a = g_aval[e];
    int i1 = atomicAdd(&g_rowpos[u], 1); g_cols[i1] = v; g_cvals[i1] = a;
    int i2 = atomicAdd(&g_rowpos[v], 1); g_cols[i2] = u; g_cvals[i2] = a;
}

__global__ void k_qscatter(const int* __restrict__ Q) {
    int q = blockIdx.x * blockDim.x + threadIdx.x;
    if (q >= EQN) return;
    int i = idx_at(Q, 2 * q);
    int idx = atomicAdd(&g_qpos[i], 1);
    g_qid[idx] = q;
}

__global__ void __launch_bounds__(256) k_row(const int* __restrict__ Q) {
    __shared__ float acc[NN];
    __shared__ float s1[8], s2[8];
    int i = blockIdx.x;
    int t = threadIdx.x;
    for (int c = t; c < NN; c += 256) acc[c] = 0.0f;
    __syncthreads();

    int rs = g_rowstart[i], re = g_rowstart[i + 1];
    float idi = g_invd[i];
    int warp = t >> 5, lane = t & 31;
    for (int jj = rs + warp; jj < re; jj += 8) {
        int j = g_cols[jj];
        float sscale = g_cvals[jj] * idi * g_invd[j];
        int js = g_rowstart[j], je = g_rowstart[j + 1];
        for (int kk = js + lane; kk < je; kk += 32)
            atomicAdd(&acc[g_cols[kk]], sscale * g_cvals[kk]);
    }
    __syncthreads();

    float srow = 0.0f, ssq = 0.0f;
    for (int c = t; c < NN; c += 256) {
        float a = acc[c];
        srow += a;
        float dd = a - g_pi[c];
        ssq = fmaf(dd, dd, ssq);
    }
#pragma unroll
    for (int o = 16; o; o >>= 1) {
        srow += __shfl_down_sync(0xffffffffu, srow, o);
        ssq  += __shfl_down_sync(0xffffffffu, ssq, o);
    }
    if (lane == 0) { s1[warp] = srow; s2[warp] = ssq; }
    __syncthreads();
    if (t == 0) {
        float S1 = 0.0f, S2 = 0.0f;
#pragma unroll
        for (int w = 0; w < 8; w++) { S1 += s1[w]; S2 += s2[w]; }
        float pii = g_pi[i];
        atomicAdd(&g_G1, (double)pii * (double)S1);
        atomicAdd(&g_G2, (double)pii * (double)pii * (double)S2);
    }
    int qs = g_qstart[i], qe = g_qstart[i + 1];
    for (int q = qs + t; q < qe; q += 256) {
        int qq = g_qid[q];
        int j1 = idx_at(Q, 2 * qq + 1);
        g_pval[qq] = acc[j1];
    }
}

__global__ void k_final(const int* __restrict__ Q, float* __restrict__ out) {
    int q = blockIdx.x * blockDim.x + threadIdx.x;
    if (q >= EQN) return;
    double n2 = (double)NN * (double)NN;
    double sp = g_sumpi;
    double mean = (g_G1 - sp * sp) / n2;
    double var = (g_G2 - n2 * mean * mean) / (n2 - 1.0);
    double istd = rsqrt(var);
    int i = idx_at(Q, 2 * q), j = idx_at(Q, 2 * q + 1);
    double r = (double)g_pi[i] * ((double)g_pval[q] - (double)g_pi[j]);
    out[q] = (float)((r - mean) * istd);
}

// ---------------- launch ----------------
extern "C" void kernel_launch(void* const* d_in, const int* in_sizes, int n_in,
                              void* d_out, int out_size) {
    const float* X  = (const float*)d_in[0];
    const float* A  = (const float*)d_in[1];
    const float* S  = (const float*)d_in[2];
    const int*   AE = (const int*)d_in[4];
    const int*   Q  = (const int*)d_in[5];
    const float* W1 = (const float*)d_in[6];
    const float* b1 = (const float*)d_in[7];
    const float* W2 = (const float*)d_in[8];
    const float* b2 = (const float*)d_in[9];
    const float* W3 = (const float*)d_in[10];
    const float* b3 = (const float*)d_in[11];
    float* out = (float*)d_out;
    int E = in_sizes[4] / 2;

    k_detect<<<1, 256>>>(AE);
    k_init<<<(NN + 255) / 256, 256>>>();
    k_xw<<<NN / 32, 128>>>(X, W1);
    k_mlp<<<(E + 31) / 32, 64>>>(X, AE, W1, b1, W2, b2, W3, b3, E);
    k_edge<<<(E + 255) / 256, 256>>>(A, S, AE, E);
    k_qcnt<<<(EQN + 255) / 256, 256>>>(Q);
    k_scan<<<1, 1024>>>();
    k_pi<<<(NN + 255) / 256, 256>>>();
    k_scatter<<<(E + 255) / 256, 256>>>(AE, E);
    k_qscatter<<<(EQN + 255) / 256, 256>>>(Q);
    k_row<<<NN, 256>>>(Q);
    k_final<<<(EQN + 255) / 256, 256>>>(Q, out);
}

// round 3
// speedup vs baseline: 1.8024x; 1.0135x over previous
#include <cuda_runtime.h>
#include <math.h>

#define NN   4096
#define DD   128
#define HH   128
#define EQN  16384
#define MAXE 131072
#define MAXNNZ 262144

// ---------------- device scratch ----------------
static __device__ float  g_vals[MAXE];
static __device__ float  g_aval[MAXE];
static __device__ float  g_d[NN];
static __device__ float  g_invd[NN];
static __device__ float  g_pi[NN];
static __device__ int    g_deg[NN];
static __device__ int    g_rowstart[NN + 1];
static __device__ int    g_rowpos[NN];
static __device__ int    g_cols[MAXNNZ];
static __device__ float  g_cvals[MAXNNZ];
static __device__ int    g_qcnt[NN];
static __device__ int    g_qstart[NN + 1];
static __device__ int    g_qpos[NN];
static __device__ int    g_qid[EQN];
static __device__ float  g_pval[EQN];
static __device__ double g_G1, g_G2, g_sumpi;
static __device__ float  g_sumd;
static __device__ float  g_XW[NN * HH];
static __device__ int    g_is64;

__device__ __forceinline__ int idx_at(const int* __restrict__ p, int k) {
    return g_is64 ? p[2 * k] : p[k];
}

// ---- packed fp32 (Blackwell f32x2) ----
__device__ __forceinline__ unsigned long long pk2(float lo, float hi) {
    unsigned long long r;
    asm("mov.b64 %0, {%1, %2};" : "=l"(r) : "f"(lo), "f"(hi));
    return r;
}
__device__ __forceinline__ void upk2(unsigned long long v, float& lo, float& hi) {
    asm("mov.b64 {%0, %1}, %2;" : "=f"(lo), "=f"(hi) : "l"(v));
}
__device__ __forceinline__ void ffma2(unsigned long long& acc,
                                      unsigned long long a, unsigned long long b) {
    asm("fma.rn.f32x2 %0, %1, %2, %0;" : "+l"(acc) : "l"(a), "l"(b));
}

// ---------------- kernels ----------------

// init + int-width detect fused (detect done by block 0)
__global__ void k_init(const int* __restrict__ AE) {
    int i = blockIdx.x * blockDim.x + threadIdx.x;
    if (i < NN) { g_d[i] = 1.0f; g_deg[i] = 1; g_qcnt[i] = 0; }
    if (i == 0) { g_G1 = 0.0; g_G2 = 0.0; g_sumpi = 0.0; }
    if (blockIdx.x == 0) {
        __shared__ int any;
        if (threadIdx.x == 0) any = 0;
        __syncthreads();
        int loc = 0;
        for (int q = threadIdx.x; q < 1024; q += blockDim.x)
            if (AE[2 * q + 1] != 0) loc = 1;
        if (loc) atomicOr(&any, 1);
        __syncthreads();
        if (threadIdx.x == 0) g_is64 = (any == 0) ? 1 : 0;
    }
}

// XW = X @ W1[0:128, :]
__global__ void __launch_bounds__(128) k_xw(const float* __restrict__ X,
                                            const float* __restrict__ W1) {
    __shared__ float xs[32 * 132];
    int t = threadIdx.x;
    int r0 = blockIdx.x * 32;
    int le = t >> 2, c = t & 3;
    const float* xr = X + (size_t)(r0 + le) * DD;
#pragma unroll
    for (int i = 0; i < 32; i++) { int k = c * 32 + i; xs[le * 132 + k] = xr[k]; }
    __syncthreads();
    float acc[32];
#pragma unroll
    for (int e = 0; e < 32; e++) acc[e] = 0.0f;
    for (int k = 0; k < 128; k++) {
        float w = W1[k * 128 + t];
#pragma unroll
        for (int e = 0; e < 32; e++) acc[e] = fmaf(w, xs[e * 132 + k], acc[e]);
    }
#pragma unroll
    for (int e = 0; e < 32; e++) g_XW[(size_t)(r0 + e) * 128 + t] = acc[e];
}

// Edge MLP, f32x2, single shared buffer (feat -> h1 -> h2).
#define FS 36
__global__ void __launch_bounds__(64, 8) k_mlp(const float* __restrict__ X,
                                               const int* __restrict__ AE,
                                               const float* __restrict__ W1,
                                               const float* __restrict__ b1,
                                               const float* __restrict__ W2,
                                               const float* __restrict__ b2,
                                               const float* __restrict__ W3,
                                               const float* __restrict__ b3,
                                               int E) {
    __shared__ float buf[128 * FS];
    __shared__ int   su[32], sv[32];
    int t = threadIdx.x;                 // 0..63
    int e0 = blockIdx.x * 32;

    // ---- feature build: |x0-x1| transposed, buf[k*FS + edge]
    {
        int le = t >> 1, c = t & 1;
        int e = e0 + le;
        int u = 0, v = 0;
        if (e < E) { u = idx_at(AE, 2 * e); v = idx_at(AE, 2 * e + 1); }
        if (c == 0) { su[le] = u; sv[le] = v; }
        const float4* x04 = (const float4*)(X + (size_t)u * DD + c * 64);
        const float4* x14 = (const float4*)(X + (size_t)v * DD + c * 64);
        bool ok = (e < E);
#pragma unroll
        for (int i = 0; i < 16; i++) {
            float4 a = x04[i], b = x14[i];
            int k = c * 64 + 4 * i;
            buf[(k + 0) * FS + le] = ok ? fabsf(a.x - b.x) : 0.0f;
            buf[(k + 1) * FS + le] = ok ? fabsf(a.y - b.y) : 0.0f;
            buf[(k + 2) * FS + le] = ok ? fabsf(a.z - b.z) : 0.0f;
            buf[(k + 3) * FS + le] = ok ? fabsf(a.w - b.w) : 0.0f;
        }
    }
    __syncthreads();

    unsigned long long accA[16], accB[16];

    // ---- layer 1
    {
        float2 bb = *(const float2*)&b1[2 * t];
#pragma unroll
        for (int p = 0; p < 16; p++) {
            int ea = 2 * p, eb = 2 * p + 1;
            float2 ua = *(const float2*)&g_XW[(size_t)su[ea] * 128 + 2 * t];
            float2 va = *(const float2*)&g_XW[(size_t)sv[ea] * 128 + 2 * t];
            float2 ub = *(const float2*)&g_XW[(size_t)su[eb] * 128 + 2 * t];
            float2 vb = *(const float2*)&g_XW[(size_t)sv[eb] * 128 + 2 * t];
            accA[p] = pk2(bb.x + ua.x + va.x, bb.x + ub.x + vb.x);
            accB[p] = pk2(bb.y + ua.y + va.y, bb.y + ub.y + vb.y);
        }
    }
#pragma unroll 2
    for (int k = 0; k < 128; k++) {
        float2 w = *(const float2*)&W1[(size_t)(128 + k) * 128 + 2 * t];
        unsigned long long w0 = pk2(w.x, w.x);
        unsigned long long w1 = pk2(w.y, w.y);
        const double2* f4 = (const double2*)&buf[k * FS];
#pragma unroll
        for (int q = 0; q < 8; q++) {
            double2 d = f4[q];
            unsigned long long flo = __double_as_longlong(d.x);
            unsigned long long fhi = __double_as_longlong(d.y);
            ffma2(accA[2 * q], flo, w0);
            ffma2(accA[2 * q + 1], fhi, w0);
            ffma2(accB[2 * q], flo, w1);
            ffma2(accB[2 * q + 1], fhi, w1);
        }
    }
    __syncthreads();   // everyone done reading feat
    // relu -> h1 (overwrite buf, transposed)
#pragma unroll
    for (int p = 0; p < 16; p++) {
        float a0, a1, c0, c1;
        upk2(accA[p], a0, a1);
        upk2(accB[p], c0, c1);
        *(float2*)&buf[(2 * t) * FS + 2 * p] =
            make_float2(fmaxf(a0, 0.0f), fmaxf(a1, 0.0f));
        *(float2*)&buf[(2 * t + 1) * FS + 2 * p] =
            make_float2(fmaxf(c0, 0.0f), fmaxf(c1, 0.0f));
    }
    __syncthreads();

    // ---- layer 2
    {
        float2 bb = *(const float2*)&b2[2 * t];
#pragma unroll
        for (int p = 0; p < 16; p++) {
            accA[p] = pk2(bb.x, bb.x);
            accB[p] = pk2(bb.y, bb.y);
        }
    }
#pragma unroll 2
    for (int k = 0; k < 128; k++) {
        float2 w = *(const float2*)&W2[(size_t)k * 128 + 2 * t];
        unsigned long long w0 = pk2(w.x, w.x);
        unsigned long long w1 = pk2(w.y, w.y);
        const double2* f4 = (const double2*)&buf[k * FS];
#pragma unroll
        for (int q = 0; q < 8; q++) {
            double2 d = f4[q];
            unsigned long long flo = __double_as_longlong(d.x);
            unsigned long long fhi = __double_as_longlong(d.y);
            ffma2(accA[2 * q], flo, w0);
            ffma2(accA[2 * q + 1], fhi, w0);
            ffma2(accB[2 * q], flo, w1);
            ffma2(accB[2 * q + 1], fhi, w1);
        }
    }
    __syncthreads();
    // relu -> h2 (overwrite buf, transposed)
#pragma unroll
    for (int p = 0; p < 16; p++) {
        float a0, a1, c0, c1;
        upk2(accA[p], a0, a1);
        upk2(accB[p], c0, c1);
        *(float2*)&buf[(2 * t) * FS + 2 * p] =
            make_float2(fmaxf(a0, 0.0f), fmaxf(a1, 0.0f));
        *(float2*)&buf[(2 * t + 1) * FS + 2 * p] =
            make_float2(fmaxf(c0, 0.0f), fmaxf(c1, 0.0f));
    }
    __syncthreads();

    // ---- head
    if (t < 32) {
        float z = b3[1] - b3[0];
        for (int k = 0; k < 128; k++) {
            float wd = W3[2 * k + 1] - W3[2 * k + 0];
            z = fmaf(buf[k * FS + t], wd, z);
        }
        int eo = e0 + t;
        if (eo < E) g_vals[eo] = 1.0f / (1.0f + __expf(-z));
    }
}

// fused: edge A_enh accumulation + query row counts
__global__ void k_edge_qcnt(const float* __restrict__ A, const float* __restrict__ S,
                            const int* __restrict__ AE, const int* __restrict__ Q,
                            int E, int EB) {
    if ((int)blockIdx.x < EB) {
        int e = blockIdx.x * 256 + threadIdx.x;
        if (e >= E) return;
        int u = idx_at(AE, 2 * e), v = idx_at(AE, 2 * e + 1);
        size_t idx = ((size_t)u << 12) + (size_t)v;
        float a = 0.5f * A[idx] + 0.25f * g_vals[e] + 0.25f * S[idx];
        g_aval[e] = a;
        atomicAdd(&g_d[u], a);
        atomicAdd(&g_d[v], a);
        atomicAdd(&g_deg[u], 1);
        atomicAdd(&g_deg[v], 1);
    } else {
        int q = (blockIdx.x - EB) * 256 + threadIdx.x;
        if (q >= EQN) return;
        atomicAdd(&g_qcnt[idx_at(Q, 2 * q)], 1);
    }
}

__global__ void __launch_bounds__(1024) k_scan() {
    __shared__ int sm[1024];
    __shared__ float sf[1024];
    int t = threadIdx.x;
    int v[4];

    int s = 0;
#pragma unroll
    for (int j = 0; j < 4; j++) { v[j] = g_deg[4 * t + j]; s += v[j]; }
    sm[t] = s;
    __syncthreads();
    for (int off = 1; off < 1024; off <<= 1) {
        int x = (t >= off) ? sm[t - off] : 0;
        __syncthreads();
        sm[t] += x;
        __syncthreads();
    }
    {
        int run = sm[t] - s;
#pragma unroll
        for (int j = 0; j < 4; j++) { g_rowstart[4 * t + j] = run; g_rowpos[4 * t + j] = run; run += v[j]; }
        if (t == 1023) g_rowstart[NN] = sm[1023];
    }
    __syncthreads();

    s = 0;
#pragma unroll
    for (int j = 0; j < 4; j++) { v[j] = g_qcnt[4 * t + j]; s += v[j]; }
    sm[t] = s;
    __syncthreads();
    for (int off = 1; off < 1024; off <<= 1) {
        int x = (t >= off) ? sm[t - off] : 0;
        __syncthreads();
        sm[t] += x;
        __syncthreads();
    }
    {
        int run = sm[t] - s;
#pragma unroll
        for (int j = 0; j < 4; j++) { g_qstart[4 * t + j] = run; g_qpos[4 * t + j] = run; run += v[j]; }
        if (t == 1023) g_qstart[NN] = sm[1023];
    }
    __syncthreads();

    float fs = 0.0f;
#pragma unroll
    for (int j = 0; j < 4; j++) fs += g_d[4 * t + j];
    sf[t] = fs;
    __syncthreads();
    for (int off = 512; off; off >>= 1) {
        if (t < off) sf[t] += sf[t + off];
        __syncthreads();
    }
    if (t == 0) g_sumd = sf[0];
}

__global__ void k_pi() {
    int i = blockIdx.x * blockDim.x + threadIdx.x;
    if (i >= NN) return;
    float di = g_d[i];
    float p = di / g_sumd;
    g_pi[i] = p;
    g_invd[i] = 1.0f / di;
    atomicAdd(&g_sumpi, (double)p);
    int idx = atomicAdd(&g_rowpos[i], 1);
    g_cols[idx] = i;
    g_cvals[idx] = 1.0f;
}

// fused: CSR scatter + query-id scatter
__global__ void k_scatter(const int* __restrict__ AE, const int* __restrict__ Q,
                          int E, int EB) {
    if ((int)blockIdx.x < EB) {
        int e = blockIdx.x * 256 + threadIdx.x;
        if (e >= E) return;
        int u = idx_at(AE, 2 * e), v = idx_at(AE, 2 * e + 1);
        float a = g_aval[e];
        int i1 = atomicAdd(&g_rowpos[u], 1); g_cols[i1] = v; g_cvals[i1] = a;
        int i2 = atomicAdd(&g_rowpos[v], 1); g_cols[i2] = u; g_cvals[i2] = a;
    } else {
        int q = (blockIdx.x - EB) * 256 + threadIdx.x;
        if (q >= EQN) return;
        int i = idx_at(Q, 2 * q);
        int idx = atomicAdd(&g_qpos[i], 1);
        g_qid[idx] = q;
    }
}

__global__ void __launch_bounds__(256) k_row(const int* __restrict__ Q) {
    __shared__ float acc[NN];
    __shared__ float s1[8], s2[8];
    int i = blockIdx.x;
    int t = threadIdx.x;
    for (int c = t; c < NN; c += 256) acc[c] = 0.0f;
    __syncthreads();

    int rs = g_rowstart[i], re = g_rowstart[i + 1];
    float idi = g_invd[i];
    int warp = t >> 5, lane = t & 31;
    for (int jj = rs + warp; jj < re; jj += 8) {
        int j = g_cols[jj];
        float sscale = g_cvals[jj] * idi * g_invd[j];
        int js = g_rowstart[j], je = g_rowstart[j + 1];
        for (int kk = js + lane; kk < je; kk += 32)
            atomicAdd(&acc[g_cols[kk]], sscale * g_cvals[kk]);
    }
    __syncthreads();

    float srow = 0.0f, ssq = 0.0f;
    for (int c = t; c < NN; c += 256) {
        float a = acc[c];
        srow += a;
        float dd = a - g_pi[c];
        ssq = fmaf(dd, dd, ssq);
    }
#pragma unroll
    for (int o = 16; o; o >>= 1) {
        srow += __shfl_down_sync(0xffffffffu, srow, o);
        ssq  += __shfl_down_sync(0xffffffffu, ssq, o);
    }
    if (lane == 0) { s1[warp] = srow; s2[warp] = ssq; }
    __syncthreads();
    if (t == 0) {
        float S1 = 0.0f, S2 = 0.0f;
#pragma unroll
        for (int w = 0; w < 8; w++) { S1 += s1[w]; S2 += s2[w]; }
        float pii = g_pi[i];
        atomicAdd(&g_G1, (double)pii * (double)S1);
        atomicAdd(&g_G2, (double)pii * (double)pii * (double)S2);
    }
    int qs = g_qstart[i], qe = g_qstart[i + 1];
    for (int q = qs + t; q < qe; q += 256) {
        int qq = g_qid[q];
        int j1 = idx_at(Q, 2 * qq + 1);
        g_pval[qq] = acc[j1];
    }
}

__global__ void k_final(const int* __restrict__ Q, float* __restrict__ out) {
    int q = blockIdx.x * blockDim.x + threadIdx.x;
    if (q >= EQN) return;
    double n2 = (double)NN * (double)NN;
    double sp = g_sumpi;
    double mean = (g_G1 - sp * sp) / n2;
    double var = (g_G2 - n2 * mean * mean) / (n2 - 1.0);
    double istd = rsqrt(var);
    int i = idx_at(Q, 2 * q), j = idx_at(Q, 2 * q + 1);
    double r = (double)g_pi[i] * ((double)g_pval[q] - (double)g_pi[j]);
    out[q] = (float)((r - mean) * istd);
}

// ---------------- launch ----------------
extern "C" void kernel_launch(void* const* d_in, const int* in_sizes, int n_in,
                              void* d_out, int out_size) {
    const float* X  = (const float*)d_in[0];
    const float* A  = (const float*)d_in[1];
    const float* S  = (const float*)d_in[2];
    const int*   AE = (const int*)d_in[4];
    const int*   Q  = (const int*)d_in[5];
    const float* W1 = (const float*)d_in[6];
    const float* b1 = (const float*)d_in[7];
    const float* W2 = (const float*)d_in[8];
    const float* b2 = (const float*)d_in[9];
    const float* W3 = (const float*)d_in[10];
    const float* b3 = (const float*)d_in[11];
    float* out = (float*)d_out;
    int E = in_sizes[4] / 2;
    int EB = (E + 255) / 256;
    int QB = (EQN + 255) / 256;

    k_init<<<(NN + 255) / 256, 256>>>(AE);
    k_xw<<<NN / 32, 128>>>(X, W1);
    k_mlp<<<(E + 31) / 32, 64>>>(X, AE, W1, b1, W2, b2, W3, b3, E);
    k_edge_qcnt<<<EB + QB, 256>>>(A, S, AE, Q, E, EB);
    k_scan<<<1, 1024>>>();
    k_pi<<<(NN + 255) / 256, 256>>>();
    k_scatter<<<EB + QB, 256>>>(AE, Q, E, EB);
    k_row<<<NN, 256>>>(Q);
    k_final<<<(EQN + 255) / 256, 256>>>(Q, out);
}